// round 6
// baseline (speedup 1.0000x reference)
#include <cuda_runtime.h>
#include <math.h>

// Problem constants
#define EDIM 128
#define FCH  64
#define WW   126           // EDIM - 2
#define A2   3
#define NCOLS 10
#define NTASK 216
#define SR   8             // batch rows per stats block
#define NPART 1024

typedef unsigned long long u64;

// ---- f32x2 packed helpers ----
__device__ __forceinline__ u64 pk(float a, float b) {
    u64 d; asm("mov.b64 %0, {%1,%2};" : "=l"(d) : "f"(a), "f"(b)); return d;
}
__device__ __forceinline__ void upk(u64 d, float& a, float& b) {
    asm("mov.b64 {%0,%1}, %2;" : "=f"(a), "=f"(b) : "l"(d));
}
__device__ __forceinline__ u64 fma2(u64 a, u64 b, u64 c) {
    u64 d; asm("fma.rn.f32x2 %0, %1, %2, %3;" : "=l"(d) : "l"(a), "l"(b), "l"(c)); return d;
}
__device__ __forceinline__ u64 mul2(u64 a, u64 b) {
    u64 d; asm("mul.rn.f32x2 %0, %1, %2;" : "=l"(d) : "l"(a), "l"(b)); return d;
}
__device__ __forceinline__ u64 add2(u64 a, u64 b) {
    u64 d; asm("add.rn.f32x2 %0, %1, %2;" : "=l"(d) : "l"(a), "l"(b)); return d;
}
__device__ __forceinline__ u64 abs2(u64 a) {   // clear sign bits of both halves
    u64 d; asm("and.b64 %0, %1, 0x7FFFFFFF7FFFFFFF;" : "=l"(d) : "l"(a)); return d;
}

// Global scratch
__device__ float g_part[NPART][NTASK];
__device__ u64   g_w1p[FCH][9];     // conv1 weights * bn1 scale, dup-packed
__device__ u64   g_b1p[FCH];        // bn1 bias, dup-packed
__device__ u64   g_w2p[FCH][9];     // conv2 weights, dup-packed
__device__ u64   g_s2p[A2][FCH];    // bn2 scale, dup-packed
__device__ u64   g_b2p[A2][FCH];    // bn2 bias, dup-packed
__device__ u64   g_fcn1p[WW][FCH];  // fcn half (conv1 part) * 0.5, dup-packed
__device__ float g_fcn2T[WW][FCH];  // fcn half (min part), transposed

// ---------------------------------------------------------------------------
// Kernel 1: tap sums S / correlations C. SR rows/block, double-buffered smem.
// 8 warps: warp -> (branch wq = warp&3, w-half = warp>>2).
// ---------------------------------------------------------------------------
__global__ void __launch_bounds__(256) stats_kernel(
    const int* __restrict__ xb,
    const float* __restrict__ er,
    const float* __restrict__ ee,
    const float* __restrict__ et,
    int B)
{
    __shared__ float s[2][9][EDIM];
    __shared__ const float* rp[SR][9];

    int tid = threadIdx.x;
    int warp = tid >> 5, lane = tid & 31;
    int wq = warp & 3, whalf = warp >> 2;
    int b0 = blockIdx.x * SR;

    for (int i = tid; i < SR * 9; i += 256) {
        int g = i / 9, r = i % 9;
        int b = b0 + g;
        const float* p;
        if (b < B) {
            const int* x = xb + (size_t)b * NCOLS;
            switch (r) {
                case 0: p = ee + (size_t)x[1] * EDIM; break;
                case 1: p = er + (size_t)x[0] * EDIM; break;
                case 2: p = ee + (size_t)x[3] * EDIM; break;
                default: p = et + (size_t)x[r + 1] * EDIM; break;
            }
        } else {
            p = (r == 0 || r == 2) ? ee : (r == 1 ? er : et);  // row 0 = zeros
        }
        rp[g][r] = p;
    }

    int rt = (wq == 0) ? 0 : 2 * wq + 1;
    int rb = (wq == 0) ? 2 : 2 * wq + 2;

    float facc[54];
    #pragma unroll
    for (int k = 0; k < 54; k++) facc[k] = 0.f;

    __syncthreads();
    for (int i = tid; i < 9 * EDIM; i += 256) {
        int r = i >> 7, c = i & 127;
        s[0][r][c] = __ldg(rp[0][r] + c);
    }
    __syncthreads();

    for (int g = 0; g < SR; g++) {
        int buf = g & 1;
        float pre[5];
        if (g + 1 < SR) {
            #pragma unroll
            for (int k = 0; k < 5; k++) {
                int i = tid + 256 * k;
                if (i < 9 * EDIM) pre[k] = __ldg(rp[g + 1][i >> 7] + (i & 127));
            }
        }
        #pragma unroll
        for (int ch = 0; ch < 2; ch++) {
            int w = whalf * 64 + ch * 32 + lane;
            if (w < WW) {
                float v[9];
                #pragma unroll
                for (int j = 0; j < 3; j++) {
                    v[j]     = s[buf][rt][w + j];
                    v[3 + j] = s[buf][1][w + j];
                    v[6 + j] = s[buf][rb][w + j];
                }
                int idx = 0;
                #pragma unroll
                for (int p = 0; p < 9; p++) {
                    facc[45 + p] += v[p];
                    #pragma unroll
                    for (int q = p; q < 9; q++) { facc[idx] += v[p] * v[q]; idx++; }
                }
            }
        }
        __syncthreads();
        if (g + 1 < SR) {
            #pragma unroll
            for (int k = 0; k < 5; k++) {
                int i = tid + 256 * k;
                if (i < 9 * EDIM) s[1 - buf][i >> 7][i & 127] = pre[k];
            }
        }
        __syncthreads();
    }

    #pragma unroll
    for (int k = 0; k < 54; k++) {
        float v = facc[k];
        #pragma unroll
        for (int off = 16; off; off >>= 1) v += __shfl_down_sync(0xffffffffu, v, off);
        facc[k] = v;
    }
    if (lane == 0) {
        int part = blockIdx.x * 2 + whalf;
        #pragma unroll
        for (int k = 0; k < 54; k++) g_part[part][wq * 54 + k] = facc[k];
    }
}

// ---------------------------------------------------------------------------
// Kernel 2: reduce partials -> BN params -> packed weights + fcn transpose.
// ---------------------------------------------------------------------------
__global__ void __launch_bounds__(256) redfin_kernel(
    const float* __restrict__ c1w, const float* __restrict__ g1, const float* __restrict__ be1,
    const float* __restrict__ c2w, const float* __restrict__ g2, const float* __restrict__ be2,
    const float* __restrict__ fcn_w,
    int B, int nparts)
{
    __shared__ double sacc[NTASK];
    __shared__ float2 ssb[256];

    int t = threadIdx.x;

    // fcn transpose + packing (independent of stats values)
    for (int i = t; i < WW * FCH; i += 256) {
        int w = i / FCH, f = i % FCH;
        float v1 = __ldg(&fcn_w[f * WW + w]);
        float v2 = __ldg(&fcn_w[FCH * WW + f * WW + w]);
        float h = 0.5f * v1;
        g_fcn1p[w][f] = pk(h, h);
        g_fcn2T[w][f] = v2;
    }

    if (t < NTASK) {
        double a0 = 0, a1 = 0, a2 = 0, a3 = 0, a4 = 0, a5 = 0, a6 = 0, a7 = 0;
        int p = 0;
        for (; p + 8 <= nparts; p += 8) {
            a0 += (double)g_part[p][t];     a1 += (double)g_part[p + 1][t];
            a2 += (double)g_part[p + 2][t]; a3 += (double)g_part[p + 3][t];
            a4 += (double)g_part[p + 4][t]; a5 += (double)g_part[p + 5][t];
            a6 += (double)g_part[p + 6][t]; a7 += (double)g_part[p + 7][t];
        }
        for (; p < nparts; p++) a0 += (double)g_part[p][t];
        sacc[t] = ((a0 + a1) + (a2 + a3)) + ((a4 + a5) + (a6 + a7));
    }
    __syncthreads();

    {
        double N = (double)B * (double)WW;
        const double* Cm; const double* Sm; const float* wf;
        float gamma, beta;
        if (t < FCH) {
            Cm = sacc; Sm = sacc + 45;
            wf = c1w + t * 9; gamma = g1[t]; beta = be1[t];
        } else {
            int u = t - FCH; int a = u / FCH, f = u % FCH;
            const double* base = sacc + 54 + a * 54;
            Cm = base; Sm = base + 45;
            wf = c2w + f * 9; gamma = g2[f]; beta = be2[f];
        }
        double wd[9];
        #pragma unroll
        for (int p = 0; p < 9; p++) wd[p] = (double)wf[p];
        double mean = 0.0;
        #pragma unroll
        for (int p = 0; p < 9; p++) mean += wd[p] * Sm[p];
        mean /= N;
        double ex2 = 0.0;
        #pragma unroll
        for (int p = 0; p < 9; p++) {
            #pragma unroll
            for (int q = 0; q < 9; q++) {
                int pp = p < q ? p : q;
                int qq = p < q ? q : p;
                int idx = pp * 9 - (pp * (pp - 1)) / 2 + (qq - pp);
                ex2 += wd[p] * wd[q] * Cm[idx];
            }
        }
        ex2 /= N;
        double var = ex2 - mean * mean;
        double rinv = 1.0 / sqrt(var + 1e-5);
        float sc = (float)((double)gamma * rinv);
        float bi = (float)((double)beta - mean * (double)gamma * rinv);
        ssb[t] = make_float2(sc, bi);
    }
    __syncthreads();

    if (t < FCH) {
        float s1 = ssb[t].x, b1 = ssb[t].y;
        #pragma unroll
        for (int j = 0; j < 9; j++) {
            float w1 = c1w[t * 9 + j] * s1;
            g_w1p[t][j] = pk(w1, w1);
            float w2 = c2w[t * 9 + j];
            g_w2p[t][j] = pk(w2, w2);
        }
        g_b1p[t] = pk(b1, b1);
    } else {
        int u = t - FCH; int a = u / FCH, f = u % FCH;
        g_s2p[a][f] = pk(ssb[t].x, ssb[t].x);
        g_b2p[a][f] = pk(ssb[t].y, ssb[t].y);
    }
}

// ---------------------------------------------------------------------------
// Kernel 3: fused conv -> BN -> relu -> min -> FC dot.
// Thread = (channel f = tid&63, batch-pair gp = tid>>6). 4 batch rows/block.
// Rows 0-2 slide via 3-phase register rotation; ht/tt rows read per step as
// interleaved LDS.128 pairs (transient). conv1 tail fully packed via
// relu(x)*fw == (x+|x|)*(fw/2).
// ---------------------------------------------------------------------------
__global__ void __launch_bounds__(128, 5) main_kernel(
    const int* __restrict__ xb,
    const float* __restrict__ er, const float* __restrict__ ee, const float* __restrict__ et,
    const float* __restrict__ fcn_b,
    float* __restrict__ out, int B)
{
    __shared__ u64 rows_pk[2][3][EDIM];        // rows 0-2, (g0,g1)-packed: 6KB
    __shared__ u64 htt[2][A2][EDIM][2];        // {ht,tt} taps interleaved: 12KB
    __shared__ const float* rp[4][9];
    __shared__ float red[4][2];

    int tid = threadIdx.x;
    int f = tid & 63, gp = tid >> 6;
    int b0 = blockIdx.x * 4;

    if (tid < 36) {
        int g = tid / 9, r = tid % 9;
        int b = b0 + g;
        const float* p;
        if (b < B) {
            const int* x = xb + (size_t)b * NCOLS;
            switch (r) {
                case 0: p = ee + (size_t)x[1] * EDIM; break;
                case 1: p = er + (size_t)x[0] * EDIM; break;
                case 2: p = ee + (size_t)x[3] * EDIM; break;
                default: p = et + (size_t)x[r + 1] * EDIM; break;
            }
        } else {
            p = (r == 0 || r == 2) ? ee : (r == 1 ? er : et);  // row 0 = zeros
        }
        rp[g][r] = p;
    }
    __syncthreads();

    // gather + pair-pack embedding rows into smem
    for (int i = tid; i < 2 * 9 * EDIM; i += 128) {
        int gq = i / (9 * EDIM);
        int rem = i % (9 * EDIM);
        int r = rem >> 7, c = rem & 127;
        float a = __ldg(rp[2 * gq][r] + c);
        float b = __ldg(rp[2 * gq + 1][r] + c);
        u64 v = pk(a, b);
        if (r < 3) rows_pk[gq][r][c] = v;
        else       htt[gq][(r - 3) >> 1][c][(r - 3) & 1] = v;
    }

    // per-thread weights (25 u64, loaded once)
    u64 W1[9], W2[9], B1, S2[A2], B2[A2];
    #pragma unroll
    for (int j = 0; j < 9; j++) { W1[j] = g_w1p[f][j]; W2[j] = g_w2p[f][j]; }
    B1 = g_b1p[f];
    #pragma unroll
    for (int a = 0; a < A2; a++) { S2[a] = g_s2p[a][f]; B2[a] = g_b2p[a][f]; }
    __syncthreads();

    const u64*   fp1 = &g_fcn1p[0][f];
    const float* fp2 = &g_fcn2T[0][f];
    u64   acc1p = 0;                 // packed conv1-path accumulator
    float acc0 = 0.f, acc1 = 0.f;    // conv2-path accumulators (scalar halves)

    u64 Wa[3], Wb[3], Wc[3];
    #pragma unroll
    for (int r = 0; r < 3; r++) {
        Wa[r] = rows_pk[gp][r][0];
        Wb[r] = rows_pk[gp][r][1];
    }

    #define STEP(A_, B_, C_, wv)                                              \
    {                                                                         \
        _Pragma("unroll")                                                     \
        for (int r = 0; r < 3; r++) C_[r] = rows_pk[gp][r][(wv) + 2];         \
        u64 fw1 = __ldg(fp1 + (wv) * FCH);                                    \
        float fw2 = __ldg(fp2 + (wv) * FCH);                                  \
        /* conv1 (pre-scaled weights, bias = B1) */                           \
        u64 c1 = fma2(W1[0], A_[0], B1);                                      \
        c1 = fma2(W1[3], A_[1], c1);                                          \
        c1 = fma2(W1[6], A_[2], c1);                                          \
        c1 = fma2(W1[1], B_[0], c1);                                          \
        c1 = fma2(W1[4], B_[1], c1);                                          \
        c1 = fma2(W1[7], B_[2], c1);                                          \
        c1 = fma2(W1[2], C_[0], c1);                                          \
        c1 = fma2(W1[5], C_[1], c1);                                          \
        c1 = fma2(W1[8], C_[2], c1);                                          \
        /* relu-dot, fully packed: (x+|x|) * (fw/2) */                        \
        acc1p = fma2(add2(c1, abs2(c1)), fw1, acc1p);                         \
        /* conv2 shared middle row */                                         \
        u64 rpt = mul2(W2[3], A_[1]);                                         \
        rpt = fma2(W2[4], B_[1], rpt);                                        \
        rpt = fma2(W2[5], C_[1], rpt);                                        \
        float ma, mb;                                                         \
        {                                                                     \
            u64 h0 = htt[gp][0][(wv)][0],     t0 = htt[gp][0][(wv)][1];       \
            u64 h1 = htt[gp][0][(wv) + 1][0], t1 = htt[gp][0][(wv) + 1][1];   \
            u64 h2 = htt[gp][0][(wv) + 2][0], t2 = htt[gp][0][(wv) + 2][1];   \
            u64 q = fma2(W2[0], h0, rpt);                                     \
            q = fma2(W2[1], h1, q);  q = fma2(W2[2], h2, q);                  \
            q = fma2(W2[6], t0, q);  q = fma2(W2[7], t1, q);                  \
            q = fma2(W2[8], t2, q);                                           \
            q = fma2(q, S2[0], B2[0]);                                        \
            upk(q, ma, mb);                                                   \
        }                                                                     \
        {                                                                     \
            u64 h0 = htt[gp][1][(wv)][0],     t0 = htt[gp][1][(wv)][1];       \
            u64 h1 = htt[gp][1][(wv) + 1][0], t1 = htt[gp][1][(wv) + 1][1];   \
            u64 h2 = htt[gp][1][(wv) + 2][0], t2 = htt[gp][1][(wv) + 2][1];   \
            u64 q = fma2(W2[0], h0, rpt);                                     \
            q = fma2(W2[1], h1, q);  q = fma2(W2[2], h2, q);                  \
            q = fma2(W2[6], t0, q);  q = fma2(W2[7], t1, q);                  \
            q = fma2(W2[8], t2, q);                                           \
            q = fma2(q, S2[1], B2[1]);                                        \
            float xa, xb_; upk(q, xa, xb_);                                   \
            ma = fminf(ma, xa); mb = fminf(mb, xb_);                          \
        }                                                                     \
        {                                                                     \
            u64 h0 = htt[gp][2][(wv)][0],     t0 = htt[gp][2][(wv)][1];       \
            u64 h1 = htt[gp][2][(wv) + 1][0], t1 = htt[gp][2][(wv) + 1][1];   \
            u64 h2 = htt[gp][2][(wv) + 2][0], t2 = htt[gp][2][(wv) + 2][1];   \
            u64 q = fma2(W2[0], h0, rpt);                                     \
            q = fma2(W2[1], h1, q);  q = fma2(W2[2], h2, q);                  \
            q = fma2(W2[6], t0, q);  q = fma2(W2[7], t1, q);                  \
            q = fma2(W2[8], t2, q);                                           \
            q = fma2(q, S2[2], B2[2]);                                        \
            float xa, xb_; upk(q, xa, xb_);                                   \
            ma = fminf(ma, xa); mb = fminf(mb, xb_);                          \
        }                                                                     \
        acc0 = fmaf(fmaxf(ma, 0.f), fw2, acc0);                               \
        acc1 = fmaf(fmaxf(mb, 0.f), fw2, acc1);                               \
    }

    for (int w = 0; w < WW; w += 3) {
        STEP(Wa, Wb, Wc, w);
        STEP(Wb, Wc, Wa, w + 1);
        STEP(Wc, Wa, Wb, w + 2);
    }
    #undef STEP

    // fold packed conv1 accumulator into scalar accumulators
    {
        float pa, pb; upk(acc1p, pa, pb);
        acc0 += pa; acc1 += pb;
    }

    // reduce over f (two warps per gp)
    int lane = tid & 31, warp = tid >> 5;
    #pragma unroll
    for (int off = 16; off; off >>= 1) {
        acc0 += __shfl_down_sync(0xffffffffu, acc0, off);
        acc1 += __shfl_down_sync(0xffffffffu, acc1, off);
    }
    if (lane == 0) { red[warp][0] = acc0; red[warp][1] = acc1; }
    __syncthreads();
    if (tid < 4) {
        int g = tid;
        int gq = g >> 1, h = g & 1;
        float tot = red[2 * gq][h] + red[2 * gq + 1][h] + __ldg(&fcn_b[0]);
        if (b0 + g < B) out[b0 + g] = tot;
    }
}

// ---------------------------------------------------------------------------
// Launch: stats -> redfin -> main
// ---------------------------------------------------------------------------
extern "C" void kernel_launch(void* const* d_in, const int* in_sizes, int n_in,
                              void* d_out, int out_size)
{
    const int*   xb  = (const int*)d_in[0];
    const float* er  = (const float*)d_in[3];
    const float* ee  = (const float*)d_in[4];
    const float* et  = (const float*)d_in[5];
    const float* c1w = (const float*)d_in[6];
    const float* g1  = (const float*)d_in[8];
    const float* be1 = (const float*)d_in[9];
    const float* c2w = (const float*)d_in[10];
    const float* g2  = (const float*)d_in[12];
    const float* be2 = (const float*)d_in[13];
    const float* fw  = (const float*)d_in[14];
    const float* fb  = (const float*)d_in[15];

    int B = in_sizes[0] / NCOLS;
    int sblocks = (B + SR - 1) / SR;
    if (sblocks * 2 > NPART) sblocks = NPART / 2;
    int nparts = sblocks * 2;

    stats_kernel<<<sblocks, 256>>>(xb, er, ee, et, B);
    redfin_kernel<<<1, 256>>>(c1w, g1, be1, c2w, g2, be2, fw, B, nparts);
    main_kernel<<<(B + 3) / 4, 128>>>(xb, er, ee, et, fb, (float*)d_out, B);
}

// round 8
// speedup vs baseline: 1.2312x; 1.2312x over previous
#include <cuda_runtime.h>
#include <math.h>

// Problem constants
#define EDIM 128
#define FCH  64
#define WW   126           // EDIM - 2
#define A2   3
#define NCOLS 10
#define NTASK 216
#define SR   8             // batch rows per stats block
#define NPART 1024

typedef unsigned long long u64;

// ---- f32x2 packed helpers ----
__device__ __forceinline__ u64 pk(float a, float b) {
    u64 d; asm("mov.b64 %0, {%1,%2};" : "=l"(d) : "f"(a), "f"(b)); return d;
}
__device__ __forceinline__ void upk(u64 d, float& a, float& b) {
    asm("mov.b64 {%0,%1}, %2;" : "=f"(a), "=f"(b) : "l"(d));
}
__device__ __forceinline__ u64 fma2(u64 a, u64 b, u64 c) {
    u64 d; asm("fma.rn.f32x2 %0, %1, %2, %3;" : "=l"(d) : "l"(a), "l"(b), "l"(c)); return d;
}
__device__ __forceinline__ u64 mul2(u64 a, u64 b) {
    u64 d; asm("mul.rn.f32x2 %0, %1, %2;" : "=l"(d) : "l"(a), "l"(b)); return d;
}
__device__ __forceinline__ u64 add2(u64 a, u64 b) {
    u64 d; asm("add.rn.f32x2 %0, %1, %2;" : "=l"(d) : "l"(a), "l"(b)); return d;
}
__device__ __forceinline__ u64 abs2(u64 a) {   // clear sign bits of both halves
    u64 d; asm("and.b64 %0, %1, 0x7FFFFFFF7FFFFFFF;" : "=l"(d) : "l"(a)); return d;
}

// Global scratch
__device__ float g_part[NPART][NTASK];
__device__ u64   g_w1p[FCH][9];     // conv1 weights * bn1 scale, dup-packed
__device__ u64   g_b1p[FCH];        // bn1 bias, dup-packed
__device__ u64   g_w2p[FCH][9];     // conv2 weights, dup-packed
__device__ u64   g_s2p[A2][FCH];    // bn2 scale, dup-packed
__device__ u64   g_b2p[A2][FCH];    // bn2 bias, dup-packed
__device__ u64   g_fcn1p[WW][FCH];  // fcn half (conv1 part) * 0.5, dup-packed
__device__ float g_fcn2T[WW][FCH];  // fcn half (min part), transposed

// ---------------------------------------------------------------------------
// Kernel 1: tap sums S / correlations C.
// Bulk-parallel: ALL SR row-sets loaded up-front (36KB smem, ~36 LDGs/thread
// in flight), single sync, then compute from smem with zero further stalls.
// 8 warps: warp -> (branch wq = warp&3, w-half = warp>>2).
// ---------------------------------------------------------------------------
__global__ void __launch_bounds__(256) stats_kernel(
    const int* __restrict__ xb,
    const float* __restrict__ er,
    const float* __restrict__ ee,
    const float* __restrict__ et,
    int B)
{
    __shared__ float s[SR][9][EDIM];      // 36 KB
    __shared__ const float* rp[SR][9];

    int tid = threadIdx.x;
    int warp = tid >> 5, lane = tid & 31;
    int wq = warp & 3, whalf = warp >> 2;
    int b0 = blockIdx.x * SR;

    if (tid < SR * 9) {
        int g = tid / 9, r = tid % 9;
        int b = b0 + g;
        const float* p;
        if (b < B) {
            const int* x = xb + (size_t)b * NCOLS;
            switch (r) {
                case 0: p = ee + (size_t)x[1] * EDIM; break;
                case 1: p = er + (size_t)x[0] * EDIM; break;
                case 2: p = ee + (size_t)x[3] * EDIM; break;
                default: p = et + (size_t)x[r + 1] * EDIM; break;
            }
        } else {
            p = (r == 0 || r == 2) ? ee : (r == 1 ? er : et);  // row 0 = zeros
        }
        rp[g][r] = p;
    }
    __syncthreads();

    // bulk gather: SR*9*EDIM floats, coalesced, max MLP
    for (int i = tid; i < SR * 9 * EDIM; i += 256) {
        int g = i / (9 * EDIM);
        int rem = i % (9 * EDIM);
        int r = rem >> 7, c = rem & 127;
        s[g][r][c] = __ldg(rp[g][r] + c);
    }
    __syncthreads();

    int rt = (wq == 0) ? 0 : 2 * wq + 1;
    int rb = (wq == 0) ? 2 : 2 * wq + 2;

    float facc[54];
    #pragma unroll
    for (int k = 0; k < 54; k++) facc[k] = 0.f;

    for (int g = 0; g < SR; g++) {
        #pragma unroll
        for (int ch = 0; ch < 2; ch++) {
            int w = whalf * 64 + ch * 32 + lane;
            if (w < WW) {
                float v[9];
                #pragma unroll
                for (int j = 0; j < 3; j++) {
                    v[j]     = s[g][rt][w + j];
                    v[3 + j] = s[g][1][w + j];
                    v[6 + j] = s[g][rb][w + j];
                }
                int idx = 0;
                #pragma unroll
                for (int p = 0; p < 9; p++) {
                    facc[45 + p] += v[p];
                    #pragma unroll
                    for (int q = p; q < 9; q++) { facc[idx] += v[p] * v[q]; idx++; }
                }
            }
        }
    }

    #pragma unroll
    for (int k = 0; k < 54; k++) {
        float v = facc[k];
        #pragma unroll
        for (int off = 16; off; off >>= 1) v += __shfl_down_sync(0xffffffffu, v, off);
        facc[k] = v;
    }
    if (lane == 0) {
        int part = blockIdx.x * 2 + whalf;
        #pragma unroll
        for (int k = 0; k < 54; k++) g_part[part][wq * 54 + k] = facc[k];
    }
}

// ---------------------------------------------------------------------------
// Kernel 2: reduce partials -> BN params -> packed weights + fcn transpose.
// ---------------------------------------------------------------------------
__global__ void __launch_bounds__(256) redfin_kernel(
    const float* __restrict__ c1w, const float* __restrict__ g1, const float* __restrict__ be1,
    const float* __restrict__ c2w, const float* __restrict__ g2, const float* __restrict__ be2,
    const float* __restrict__ fcn_w,
    int B, int nparts)
{
    __shared__ double sacc[NTASK];
    __shared__ float2 ssb[256];

    int t = threadIdx.x;

    // fcn transpose + packing (independent of stats values)
    for (int i = t; i < WW * FCH; i += 256) {
        int w = i / FCH, f = i % FCH;
        float v1 = __ldg(&fcn_w[f * WW + w]);
        float v2 = __ldg(&fcn_w[FCH * WW + f * WW + w]);
        float h = 0.5f * v1;
        g_fcn1p[w][f] = pk(h, h);
        g_fcn2T[w][f] = v2;
    }

    if (t < NTASK) {
        double a0 = 0, a1 = 0, a2 = 0, a3 = 0, a4 = 0, a5 = 0, a6 = 0, a7 = 0;
        int p = 0;
        for (; p + 8 <= nparts; p += 8) {
            a0 += (double)g_part[p][t];     a1 += (double)g_part[p + 1][t];
            a2 += (double)g_part[p + 2][t]; a3 += (double)g_part[p + 3][t];
            a4 += (double)g_part[p + 4][t]; a5 += (double)g_part[p + 5][t];
            a6 += (double)g_part[p + 6][t]; a7 += (double)g_part[p + 7][t];
        }
        for (; p < nparts; p++) a0 += (double)g_part[p][t];
        sacc[t] = ((a0 + a1) + (a2 + a3)) + ((a4 + a5) + (a6 + a7));
    }
    __syncthreads();

    {
        double N = (double)B * (double)WW;
        const double* Cm; const double* Sm; const float* wf;
        float gamma, beta;
        if (t < FCH) {
            Cm = sacc; Sm = sacc + 45;
            wf = c1w + t * 9; gamma = g1[t]; beta = be1[t];
        } else {
            int u = t - FCH; int a = u / FCH, f = u % FCH;
            const double* base = sacc + 54 + a * 54;
            Cm = base; Sm = base + 45;
            wf = c2w + f * 9; gamma = g2[f]; beta = be2[f];
        }
        double wd[9];
        #pragma unroll
        for (int p = 0; p < 9; p++) wd[p] = (double)wf[p];
        double mean = 0.0;
        #pragma unroll
        for (int p = 0; p < 9; p++) mean += wd[p] * Sm[p];
        mean /= N;
        double ex2 = 0.0;
        #pragma unroll
        for (int p = 0; p < 9; p++) {
            #pragma unroll
            for (int q = 0; q < 9; q++) {
                int pp = p < q ? p : q;
                int qq = p < q ? q : p;
                int idx = pp * 9 - (pp * (pp - 1)) / 2 + (qq - pp);
                ex2 += wd[p] * wd[q] * Cm[idx];
            }
        }
        ex2 /= N;
        double var = ex2 - mean * mean;
        double rinv = 1.0 / sqrt(var + 1e-5);
        float sc = (float)((double)gamma * rinv);
        float bi = (float)((double)beta - mean * (double)gamma * rinv);
        ssb[t] = make_float2(sc, bi);
    }
    __syncthreads();

    if (t < FCH) {
        float s1 = ssb[t].x, b1 = ssb[t].y;
        #pragma unroll
        for (int j = 0; j < 9; j++) {
            float w1 = c1w[t * 9 + j] * s1;
            g_w1p[t][j] = pk(w1, w1);
            float w2 = c2w[t * 9 + j];
            g_w2p[t][j] = pk(w2, w2);
        }
        g_b1p[t] = pk(b1, b1);
    } else {
        int u = t - FCH; int a = u / FCH, f = u % FCH;
        g_s2p[a][f] = pk(ssb[t].x, ssb[t].x);
        g_b2p[a][f] = pk(ssb[t].y, ssb[t].y);
    }
}

// ---------------------------------------------------------------------------
// Kernel 3: fused conv -> BN -> relu -> min -> FC dot  (R4 structure).
// Thread = (channel f = tid&63, batch-pair gp = tid>>6). 4 batch rows/block.
// ALL 9 rows slide via 3-phase register rotation (27 u64 window regs).
// conv1 tail fully packed via relu(x)*fw == (x+|x|)*(fw/2)  [bit-exact].
// ---------------------------------------------------------------------------
__global__ void __launch_bounds__(128, 4) main_kernel(
    const int* __restrict__ xb,
    const float* __restrict__ er, const float* __restrict__ ee, const float* __restrict__ et,
    const float* __restrict__ fcn_b,
    float* __restrict__ out, int B)
{
    __shared__ u64 rows_pk[2][9][EDIM];   // (g0,g1)-packed embedding rows, 18KB
    __shared__ const float* rp[4][9];
    __shared__ float red[4][2];

    int tid = threadIdx.x;
    int f = tid & 63, gp = tid >> 6;
    int b0 = blockIdx.x * 4;

    if (tid < 36) {
        int g = tid / 9, r = tid % 9;
        int b = b0 + g;
        const float* p;
        if (b < B) {
            const int* x = xb + (size_t)b * NCOLS;
            switch (r) {
                case 0: p = ee + (size_t)x[1] * EDIM; break;
                case 1: p = er + (size_t)x[0] * EDIM; break;
                case 2: p = ee + (size_t)x[3] * EDIM; break;
                default: p = et + (size_t)x[r + 1] * EDIM; break;
            }
        } else {
            p = (r == 0 || r == 2) ? ee : (r == 1 ? er : et);  // row 0 = zeros
        }
        rp[g][r] = p;
    }
    __syncthreads();

    // gather + pair-pack embedding rows into smem
    for (int i = tid; i < 2 * 9 * EDIM; i += 128) {
        int gq = i / (9 * EDIM);
        int rem = i % (9 * EDIM);
        int r = rem >> 7, c = rem & 127;
        float a = __ldg(rp[2 * gq][r] + c);
        float b = __ldg(rp[2 * gq + 1][r] + c);
        rows_pk[gq][r][c] = pk(a, b);
    }

    // per-thread weights (25 u64, loaded once)
    u64 W1[9], W2[9], B1, S2[A2], B2[A2];
    #pragma unroll
    for (int j = 0; j < 9; j++) { W1[j] = g_w1p[f][j]; W2[j] = g_w2p[f][j]; }
    B1 = g_b1p[f];
    #pragma unroll
    for (int a = 0; a < A2; a++) { S2[a] = g_s2p[a][f]; B2[a] = g_b2p[a][f]; }
    __syncthreads();

    const u64*   fp1 = &g_fcn1p[0][f];
    const float* fp2 = &g_fcn2T[0][f];
    u64   acc1p = 0;                 // packed conv1-path accumulator
    float acc0 = 0.f, acc1 = 0.f;    // scalar accumulators (conv2 path)

    u64 Wa[9], Wb[9], Wc[9];
    #pragma unroll
    for (int r = 0; r < 9; r++) {
        Wa[r] = rows_pk[gp][r][0];
        Wb[r] = rows_pk[gp][r][1];
    }

    #define STEP(A_, B_, C_, wv)                                              \
    {                                                                         \
        _Pragma("unroll")                                                     \
        for (int r = 0; r < 9; r++) C_[r] = rows_pk[gp][r][(wv) + 2];         \
        u64 fw1 = __ldg(fp1 + (wv) * FCH);                                    \
        float fw2 = __ldg(fp2 + (wv) * FCH);                                  \
        /* conv1 (pre-scaled weights, bias = B1) */                           \
        u64 c1 = fma2(W1[0], A_[0], B1);                                      \
        c1 = fma2(W1[3], A_[1], c1);                                          \
        c1 = fma2(W1[6], A_[2], c1);                                          \
        c1 = fma2(W1[1], B_[0], c1);                                          \
        c1 = fma2(W1[4], B_[1], c1);                                          \
        c1 = fma2(W1[7], B_[2], c1);                                          \
        c1 = fma2(W1[2], C_[0], c1);                                          \
        c1 = fma2(W1[5], C_[1], c1);                                          \
        c1 = fma2(W1[8], C_[2], c1);                                          \
        /* relu-dot, fully packed: (x+|x|) * (fw/2) */                        \
        acc1p = fma2(add2(c1, abs2(c1)), fw1, acc1p);                         \
        /* conv2 shared middle row */                                         \
        u64 rpt = mul2(W2[3], A_[1]);                                         \
        rpt = fma2(W2[4], B_[1], rpt);                                        \
        rpt = fma2(W2[5], C_[1], rpt);                                        \
        u64 u0, u1, u2;                                                       \
        {                                                                     \
            u64 t = fma2(W2[0], A_[3], rpt);                                  \
            t = fma2(W2[1], B_[3], t);  t = fma2(W2[2], C_[3], t);            \
            t = fma2(W2[6], A_[4], t);  t = fma2(W2[7], B_[4], t);            \
            t = fma2(W2[8], C_[4], t);                                        \
            u0 = fma2(t, S2[0], B2[0]);                                       \
        }                                                                     \
        {                                                                     \
            u64 t = fma2(W2[0], A_[5], rpt);                                  \
            t = fma2(W2[1], B_[5], t);  t = fma2(W2[2], C_[5], t);            \
            t = fma2(W2[6], A_[6], t);  t = fma2(W2[7], B_[6], t);            \
            t = fma2(W2[8], C_[6], t);                                        \
            u1 = fma2(t, S2[1], B2[1]);                                       \
        }                                                                     \
        {                                                                     \
            u64 t = fma2(W2[0], A_[7], rpt);                                  \
            t = fma2(W2[1], B_[7], t);  t = fma2(W2[2], C_[7], t);            \
            t = fma2(W2[6], A_[8], t);  t = fma2(W2[7], B_[8], t);            \
            t = fma2(W2[8], C_[8], t);                                        \
            u2 = fma2(t, S2[2], B2[2]);                                       \
        }                                                                     \
        float x0, y0, x1, y1, x2, y2;                                         \
        upk(u0, x0, y0); upk(u1, x1, y1); upk(u2, x2, y2);                    \
        float ma = fminf(fminf(x0, x1), x2);                                  \
        float mb = fminf(fminf(y0, y1), y2);                                  \
        acc0 = fmaf(fmaxf(ma, 0.f), fw2, acc0);                               \
        acc1 = fmaf(fmaxf(mb, 0.f), fw2, acc1);                               \
    }

    #pragma unroll 2
    for (int w = 0; w < WW; w += 3) {
        STEP(Wa, Wb, Wc, w);
        STEP(Wb, Wc, Wa, w + 1);
        STEP(Wc, Wa, Wb, w + 2);
    }
    #undef STEP

    // fold packed conv1 accumulator into scalar accumulators
    {
        float pa, pb; upk(acc1p, pa, pb);
        acc0 += pa; acc1 += pb;
    }

    // reduce over f (two warps per gp)
    int lane = tid & 31, warp = tid >> 5;
    #pragma unroll
    for (int off = 16; off; off >>= 1) {
        acc0 += __shfl_down_sync(0xffffffffu, acc0, off);
        acc1 += __shfl_down_sync(0xffffffffu, acc1, off);
    }
    if (lane == 0) { red[warp][0] = acc0; red[warp][1] = acc1; }
    __syncthreads();
    if (tid < 4) {
        int g = tid;
        int gq = g >> 1, h = g & 1;
        float tot = red[2 * gq][h] + red[2 * gq + 1][h] + __ldg(&fcn_b[0]);
        if (b0 + g < B) out[b0 + g] = tot;
    }
}

// ---------------------------------------------------------------------------
// Launch: stats -> redfin -> main
// ---------------------------------------------------------------------------
extern "C" void kernel_launch(void* const* d_in, const int* in_sizes, int n_in,
                              void* d_out, int out_size)
{
    const int*   xb  = (const int*)d_in[0];
    const float* er  = (const float*)d_in[3];
    const float* ee  = (const float*)d_in[4];
    const float* et  = (const float*)d_in[5];
    const float* c1w = (const float*)d_in[6];
    const float* g1  = (const float*)d_in[8];
    const float* be1 = (const float*)d_in[9];
    const float* c2w = (const float*)d_in[10];
    const float* g2  = (const float*)d_in[12];
    const float* be2 = (const float*)d_in[13];
    const float* fw  = (const float*)d_in[14];
    const float* fb  = (const float*)d_in[15];

    int B = in_sizes[0] / NCOLS;
    int sblocks = (B + SR - 1) / SR;
    if (sblocks * 2 > NPART) sblocks = NPART / 2;
    int nparts = sblocks * 2;

    stats_kernel<<<sblocks, 256>>>(xb, er, ee, et, B);
    redfin_kernel<<<1, 256>>>(c1w, g1, be1, c2w, g2, be2, fw, B, nparts);
    main_kernel<<<(B + 3) / 4, 128>>>(xb, er, ee, et, fb, (float*)d_out, B);
}